// round 4
// baseline (speedup 1.0000x reference)
#include <cuda_runtime.h>
#include <cuda_bf16.h>

// Problem constants (fixed by setup_inputs)
#define BB 8
#define DD 32
#define NN 131072
#define KK 64
#define DP 33            // padded row for means (+count semantics elsewhere)
#define NT 256           // points per chunk (== blockDim)
#define G1 64            // blocks per batch, pass1
#define IGNORE_IDX (-100)
#define DELTA_V 0.5f
#define DELTA_D 1.5f

// ---- scratch (allocation-free: __device__ globals) ----
__device__ float g_sum[BB * KK * DD];   // per-batch per-cluster feature sums
__device__ float g_cnt[BB * KK];        // per-batch per-cluster counts
__device__ float g_mu [BB * KK * DD];   // cluster means
__device__ float g_var[BB * KK];        // per-cluster hinged variance sums
__device__ float g_ninst[BB];
__device__ float g_ldist[BB];
__device__ float g_lreg [BB];

// ---------------------------------------------------------------------------
__global__ void k_zero() {
    int t = blockIdx.x * blockDim.x + threadIdx.x;
    int total = BB * KK * DD;
    if (t < total) g_sum[t] = 0.0f;
    if (t < BB * KK) { g_cnt[t] = 0.0f; g_var[t] = 0.0f; }
    if (t < BB) { g_ninst[t] = 0.0f; g_ldist[t] = 0.0f; g_lreg[t] = 0.0f; }
}

// ---------------------------------------------------------------------------
// Pass 1 (v3): register-resident segment sums, ZERO atomics in hot loop.
// Warp w owns clusters [8w, 8w+8); lane l owns feature d=l.
// Tile: XOR-swizzled d-major s_tile[d*256 + (n^d)]:
//   - fill: warp-uniform d -> conflict-free stores
//   - read: column n fixed, lane=d varies -> (n^lane) mod 32 distinct -> conflict-free
// Matching points found via warp-uniform ballot + bit-scan (no divergent branches).
// grid = (G1, BB), block = 256.
__global__ void __launch_bounds__(256) k_pass1(const float* __restrict__ emb,
                                               const int*   __restrict__ cls,
                                               const int*   __restrict__ inst) {
    __shared__ float s_tile[DD * 256];   // 32 KB
    __shared__ int   s_id[NT];

    const int b     = blockIdx.y;
    const int tid   = threadIdx.x;
    const int w     = tid >> 5;
    const int lane  = tid & 31;
    const int kbase = w << 3;            // 8 clusters per warp
    const float one = (lane == 0) ? 1.0f : 0.0f;

    float acc[8] = {0,0,0,0,0,0,0,0};
    float cnt[8] = {0,0,0,0,0,0,0,0};

    const float* eb = emb  + (size_t)b * DD * NN;
    const int*   cb = cls  + (size_t)b * NN;
    const int*   ib = inst + (size_t)b * NN;

    const int chunk_stride = gridDim.x * NT;
    for (int n0 = blockIdx.x * NT; n0 < NN; n0 += chunk_stride) {
        __syncthreads();   // previous chunk's readers done

        // ids for this chunk (one per thread)
        {
            int c = cb[n0 + tid];
            s_id[tid] = (c == IGNORE_IDX) ? -1 : ((c == 1) ? 0 : ib[n0 + tid]);
        }
        // fill tile: 8 float4 loads per thread; XOR-swizzled scalar stores
        #pragma unroll
        for (int r = 0; r < 8; r++) {
            int i  = r * 256 + tid;      // 0..2047
            int d  = i >> 6;             // 64 float4 per d-row
            int n4 = i & 63;
            float4 v = ((const float4*)(eb + (size_t)d * NN + n0))[n4];
            int base = (d << 8);
            int nb   = n4 << 2;
            s_tile[base + ((nb + 0) ^ d)] = v.x;
            s_tile[base + ((nb + 1) ^ d)] = v.y;
            s_tile[base + ((nb + 2) ^ d)] = v.z;
            s_tile[base + ((nb + 3) ^ d)] = v.w;
        }
        __syncthreads();

        // scan all 256 points; keep only those in this warp's cluster range
        #pragma unroll
        for (int g = 0; g < 8; g++) {
            int myid = s_id[(g << 5) + lane];
            bool inr = (myid >= kbase) && (myid < kbase + 8);
            unsigned m = __ballot_sync(0xffffffffu, inr);
            while (m) {
                int p = __ffs(m) - 1;
                m &= m - 1;
                int id = __shfl_sync(0xffffffffu, myid, p);
                float val = s_tile[(lane << 8) + (((g << 5) + p) ^ lane)];
                int kl = id - kbase;
                #pragma unroll
                for (int j = 0; j < 8; j++)
                    if (kl == j) { acc[j] += val; cnt[j] += one; }
            }
        }
    }

    // flush register accumulators: coalesced global atomics (once per block)
    #pragma unroll
    for (int j = 0; j < 8; j++) {
        atomicAdd(&g_sum[(size_t)(b * KK + kbase + j) * DD + lane], acc[j]);
        if (lane == 0 && cnt[j] != 0.0f)
            atomicAdd(&g_cnt[b * KK + kbase + j], cnt[j]);
    }
}

// ---------------------------------------------------------------------------
// Pass 2: means, present mask, n_inst, pairwise hinge (l_dist), l_reg.
// grid = B, block = 256.
__global__ void k_pass2() {
    const int b = blockIdx.x;
    const int tid = threadIdx.x;
    __shared__ float s_mu[KK * DP];
    __shared__ float s_cnt[KK];
    __shared__ int   s_pres[KK];
    __shared__ float red0[256], red1[256], red2[256];

    if (tid < KK) {
        float c = g_cnt[b * KK + tid];
        s_cnt[tid] = c;
        s_pres[tid] = (c > 0.0f) ? 1 : 0;
    }
    __syncthreads();

    for (int i = tid; i < KK * DD; i += blockDim.x) {
        int k = i / DD, d = i - k * DD;
        float m = g_sum[b * KK * DD + i] / (s_cnt[k] + 1e-8f);
        g_mu[b * KK * DD + i] = m;
        s_mu[k * DP + d] = m;
    }
    __syncthreads();

    float np = 0.0f, lreg = 0.0f, ldist = 0.0f;
    for (int k = tid; k < KK; k += blockDim.x) np += (float)s_pres[k];
    for (int i = tid; i < KK * DD; i += blockDim.x) {
        int k = i / DD, d = i - k * DD;
        if (s_pres[k]) lreg += fabsf(s_mu[k * DP + d]);
    }
    for (int p = tid; p < KK * KK; p += blockDim.x) {
        int i = p >> 6, j = p & 63;
        if (i != j && s_pres[i] && s_pres[j]) {
            float dsum = 0.0f;
            #pragma unroll
            for (int d = 0; d < DD; d++)
                dsum += fabsf(s_mu[i * DP + d] - s_mu[j * DP + d]);
            float h = fmaxf(2.0f * DELTA_D - dsum, 0.0f);
            ldist += h * h;
        }
    }
    red0[tid] = np; red1[tid] = lreg; red2[tid] = ldist;
    __syncthreads();
    for (int off = 128; off > 0; off >>= 1) {
        if (tid < off) {
            red0[tid] += red0[tid + off];
            red1[tid] += red1[tid + off];
            red2[tid] += red2[tid + off];
        }
        __syncthreads();
    }
    if (tid == 0) {
        float npres  = red0[0];
        float n_inst = fmaxf(npres, 1.0f);
        float npairs = npres * npres - npres;
        g_ninst[b] = n_inst;
        g_lreg[b]  = red1[0] / n_inst;
        g_ldist[b] = (npairs > 0.0f) ? red2[0] / fmaxf(npairs, 1.0f) : 0.0f;
    }
}

// ---------------------------------------------------------------------------
// Pass 3 (v3): float2 over n — 2 points/thread, grid-stride, low register
// pressure (the float4 version regressed: occ 82%->67%).
// grid = (128, BB), block = 256.
__global__ void __launch_bounds__(256) k_pass3(const float* __restrict__ emb,
                                               const int*   __restrict__ cls,
                                               const int*   __restrict__ inst) {
    __shared__ float s_mu[KK * DP];
    __shared__ float s_var[KK];
    const int b = blockIdx.y;

    for (int i = threadIdx.x; i < KK * DD; i += blockDim.x) {
        int k = i / DD, d = i - k * DD;
        s_mu[k * DP + d] = g_mu[b * KK * DD + i];
    }
    if (threadIdx.x < KK) s_var[threadIdx.x] = 0.0f;
    __syncthreads();

    const float* eb = emb  + (size_t)b * DD * NN;
    const int*   cb = cls  + (size_t)b * NN;
    const int*   ib = inst + (size_t)b * NN;

    const int stride2 = gridDim.x * blockDim.x;
    for (int n2 = blockIdx.x * blockDim.x + threadIdx.x; n2 < NN / 2; n2 += stride2) {
        int2 c2 = ((const int2*)cb)[n2];
        int2 i2 = ((const int2*)ib)[n2];
        int id0 = (c2.x == IGNORE_IDX) ? -1 : ((c2.x == 1) ? 0 : i2.x);
        int id1 = (c2.y == IGNORE_IDX) ? -1 : ((c2.y == 1) ? 0 : i2.y);
        const float* m0 = &s_mu[(id0 < 0 ? 0 : id0) * DP];
        const float* m1 = &s_mu[(id1 < 0 ? 0 : id1) * DP];

        float a0 = 0.0f, a1 = 0.0f;
        #pragma unroll
        for (int d = 0; d < DD; d++) {
            float2 v = ((const float2*)(eb + (size_t)d * NN))[n2];
            a0 += fabsf(v.x - m0[d]);
            a1 += fabsf(v.y - m1[d]);
        }
        if (id0 >= 0) { float h = fmaxf(a0 - DELTA_V, 0.0f); atomicAdd(&s_var[id0], h * h); }
        if (id1 >= 0) { float h = fmaxf(a1 - DELTA_V, 0.0f); atomicAdd(&s_var[id1], h * h); }
    }
    __syncthreads();
    if (threadIdx.x < KK) {
        float v = s_var[threadIdx.x];
        if (v != 0.0f) atomicAdd(&g_var[b * KK + threadIdx.x], v);
    }
}

// ---------------------------------------------------------------------------
// Pass 4: finalize 4 output scalars (means over batch).
__global__ void k_pass4(float* __restrict__ out, int out_size) {
    __shared__ float acc[4];
    if (threadIdx.x < 4) acc[threadIdx.x] = 0.0f;
    __syncthreads();
    if (threadIdx.x < BB) {
        const int b = threadIdx.x;
        float lvar = 0.0f;
        for (int k = 0; k < KK; k++)
            lvar += g_var[b * KK + k] / (g_cnt[b * KK + k] + 1e-8f);
        lvar /= g_ninst[b];
        float lv = 1.0f   * lvar;        // PARAM_VAR
        float ld = 1.0f   * g_ldist[b];  // PARAM_DIST
        float lr = 0.001f * g_lreg[b];   // PARAM_REG
        float loss = lv + ld + lr;       // LOSS_WEIGHT = 1
        atomicAdd(&acc[0], loss / BB);
        atomicAdd(&acc[1], lv   / BB);
        atomicAdd(&acc[2], ld   / BB);
        atomicAdd(&acc[3], lr   / BB);
    }
    __syncthreads();
    if (threadIdx.x < 4 && threadIdx.x < out_size)
        out[threadIdx.x] = acc[threadIdx.x];
}

// ---------------------------------------------------------------------------
extern "C" void kernel_launch(void* const* d_in, const int* in_sizes, int n_in,
                              void* d_out, int out_size) {
    const float* emb  = (const float*)d_in[0];
    const int*   cls  = (const int*)  d_in[1];
    const int*   inst = (const int*)  d_in[2];
    float* out = (float*)d_out;

    (void)in_sizes; (void)n_in;

    k_zero<<<(BB * KK * DD + 255) / 256, 256>>>();

    dim3 grid1(G1, BB);
    k_pass1<<<grid1, 256>>>(emb, cls, inst);

    k_pass2<<<BB, 256>>>();

    dim3 grid3(128, BB);
    k_pass3<<<grid3, 256>>>(emb, cls, inst);

    k_pass4<<<1, 64>>>(out, out_size);
}

// round 7
// speedup vs baseline: 1.4824x; 1.4824x over previous
#include <cuda_runtime.h>
#include <cuda_bf16.h>

// Problem constants (fixed by setup_inputs)
#define BB 8
#define DD 32
#define NN 131072
#define KK 64
#define DP 33            // padded row for means in pass2/3
#define NT 256           // points per chunk (== blockDim)
#define G1 37            // blocks per batch, pass1 (37*8=296 = 2/SM * 148 SMs, one wave)
#define IGNORE_IDX (-100)
#define DELTA_V 0.5f
#define DELTA_D 1.5f

// pass1 dynamic smem layout (bytes)
#define SM_TILE   (DD * 256 * 4)          // 32768
#define SM_ACC    (8 * KK * 32 * 4)       // 65536 (8 warp-private [K][32] copies)
#define SM_IDS    (NT * 4)                // 1024
#define SM_CNT    (KK * 4)                // 256
#define SM_TOTAL  (SM_TILE + SM_ACC + SM_IDS + SM_CNT)   // 99584

// ---- scratch (allocation-free: __device__ globals) ----
__device__ float g_sum[BB * KK * DD];
__device__ float g_cnt[BB * KK];
__device__ float g_mu [BB * KK * DD];
__device__ float g_var[BB * KK];
__device__ float g_ninst[BB];
__device__ float g_ldist[BB];
__device__ float g_lreg [BB];

// ---------------------------------------------------------------------------
__global__ void k_zero() {
    int t = blockIdx.x * blockDim.x + threadIdx.x;
    int total = BB * KK * DD;
    if (t < total) g_sum[t] = 0.0f;
    if (t < BB * KK) { g_cnt[t] = 0.0f; g_var[t] = 0.0f; }
    if (t < BB) { g_ninst[t] = 0.0f; g_ldist[t] = 0.0f; g_lreg[t] = 0.0f; }
}

// ---------------------------------------------------------------------------
// Pass 1 (v4): warp-per-point with warp-private NON-ATOMIC smem accumulators.
// - tile: v3's XOR-swizzled d-major layout (proven): fill conflict-free-ish,
//   column reads fully conflict-free.
// - warp w owns acc copy w: s_acc[w][id][lane]; per point one LDS+FADD+STS
//   (consecutive addresses -> conflict-free; warp-disjoint -> race-free;
//   same-thread same-address ordering is HW-guaranteed).
// - counts: ONE block-shared atomicAdd per point (vs 33 lane-ops in v2).
// grid = (G1, BB), block = 256, dynamic smem = SM_TOTAL.
__global__ void __launch_bounds__(256) k_pass1(const float* __restrict__ emb,
                                               const int*   __restrict__ cls,
                                               const int*   __restrict__ inst) {
    extern __shared__ float smem[];
    float* s_tile = smem;                          // [DD][256] swizzled
    float* s_acc  = smem + DD * 256;               // [8][KK][32]
    int*   s_id   = (int*)(s_acc + 8 * KK * 32);   // [256]
    float* s_cnt  = (float*)(s_id + NT);           // [KK]

    const int b    = blockIdx.y;
    const int tid  = threadIdx.x;
    const int w    = tid >> 5;
    const int lane = tid & 31;

    for (int i = tid; i < 8 * KK * 32; i += 256) s_acc[i] = 0.0f;
    if (tid < KK) s_cnt[tid] = 0.0f;

    const float* eb = emb  + (size_t)b * DD * NN;
    const int*   cb = cls  + (size_t)b * NN;
    const int*   ib = inst + (size_t)b * NN;

    float* accw = &s_acc[(w << 11)];   // w * KK * 32

    const int chunk_stride = gridDim.x * NT;
    for (int n0 = blockIdx.x * NT; n0 < NN; n0 += chunk_stride) {
        __syncthreads();   // prev chunk readers done (covers init on iter 0)

        // ids + counts for this chunk (one point per thread)
        {
            int c  = cb[n0 + tid];
            int id = (c == IGNORE_IDX) ? -1 : ((c == 1) ? 0 : ib[n0 + tid]);
            s_id[tid] = id;
            if (id >= 0) atomicAdd(&s_cnt[id], 1.0f);
        }
        // fill tile: 8 float4 loads per thread, XOR-swizzled scalar stores
        #pragma unroll
        for (int r = 0; r < 8; r++) {
            int i  = r * 256 + tid;
            int d  = i >> 6;
            int n4 = i & 63;
            float4 v = ((const float4*)(eb + (size_t)d * NN + n0))[n4];
            int base = (d << 8);
            int nb   = n4 << 2;
            s_tile[base + ((nb + 0) ^ d)] = v.x;
            s_tile[base + ((nb + 1) ^ d)] = v.y;
            s_tile[base + ((nb + 2) ^ d)] = v.z;
            s_tile[base + ((nb + 3) ^ d)] = v.w;
        }
        __syncthreads();

        // warp w processes points [w*32, w*32+32): non-atomic RMW into accw
        #pragma unroll 8
        for (int p = 0; p < 32; p++) {
            int n  = (w << 5) + p;
            int id = s_id[n];                              // broadcast LDS
            if (id >= 0) {                                 // warp-uniform branch
                float val = s_tile[(lane << 8) + (n ^ lane)];  // conflict-free
                float* a = &accw[(id << 5) + lane];            // consecutive
                *a += val;                                     // LDS+FADD+STS
            }
        }
    }
    __syncthreads();

    // flush: reduce 8 warp copies, one global atomic per (k,d)
    for (int i = tid; i < KK * 32; i += 256) {
        float v = 0.0f;
        #pragma unroll
        for (int c = 0; c < 8; c++) v += s_acc[(c << 11) + i];
        if (v != 0.0f) atomicAdd(&g_sum[(size_t)b * KK * DD + i], v);
    }
    if (tid < KK) {
        float v = s_cnt[tid];
        if (v != 0.0f) atomicAdd(&g_cnt[b * KK + tid], v);
    }
}

// ---------------------------------------------------------------------------
// Pass 2: means, present mask, n_inst, pairwise hinge (l_dist), l_reg.
__global__ void k_pass2() {
    const int b = blockIdx.x;
    const int tid = threadIdx.x;
    __shared__ float s_mu[KK * DP];
    __shared__ float s_cnt[KK];
    __shared__ int   s_pres[KK];
    __shared__ float red0[256], red1[256], red2[256];

    if (tid < KK) {
        float c = g_cnt[b * KK + tid];
        s_cnt[tid] = c;
        s_pres[tid] = (c > 0.0f) ? 1 : 0;
    }
    __syncthreads();

    for (int i = tid; i < KK * DD; i += blockDim.x) {
        int k = i / DD, d = i - k * DD;
        float m = g_sum[b * KK * DD + i] / (s_cnt[k] + 1e-8f);
        g_mu[b * KK * DD + i] = m;
        s_mu[k * DP + d] = m;
    }
    __syncthreads();

    float np = 0.0f, lreg = 0.0f, ldist = 0.0f;
    for (int k = tid; k < KK; k += blockDim.x) np += (float)s_pres[k];
    for (int i = tid; i < KK * DD; i += blockDim.x) {
        int k = i / DD, d = i - k * DD;
        if (s_pres[k]) lreg += fabsf(s_mu[k * DP + d]);
    }
    for (int p = tid; p < KK * KK; p += blockDim.x) {
        int i = p >> 6, j = p & 63;
        if (i != j && s_pres[i] && s_pres[j]) {
            float dsum = 0.0f;
            #pragma unroll
            for (int d = 0; d < DD; d++)
                dsum += fabsf(s_mu[i * DP + d] - s_mu[j * DP + d]);
            float h = fmaxf(2.0f * DELTA_D - dsum, 0.0f);
            ldist += h * h;
        }
    }
    red0[tid] = np; red1[tid] = lreg; red2[tid] = ldist;
    __syncthreads();
    for (int off = 128; off > 0; off >>= 1) {
        if (tid < off) {
            red0[tid] += red0[tid + off];
            red1[tid] += red1[tid + off];
            red2[tid] += red2[tid + off];
        }
        __syncthreads();
    }
    if (tid == 0) {
        float npres  = red0[0];
        float n_inst = fmaxf(npres, 1.0f);
        float npairs = npres * npres - npres;
        g_ninst[b] = n_inst;
        g_lreg[b]  = red1[0] / n_inst;
        g_ldist[b] = (npairs > 0.0f) ? red2[0] / fmaxf(npairs, 1.0f) : 0.0f;
    }
}

// ---------------------------------------------------------------------------
// Pass 3 (v3, best measured: 28.1us, DRAM 68%): float2, 2 pts/thread.
__global__ void __launch_bounds__(256) k_pass3(const float* __restrict__ emb,
                                               const int*   __restrict__ cls,
                                               const int*   __restrict__ inst) {
    __shared__ float s_mu[KK * DP];
    __shared__ float s_var[KK];
    const int b = blockIdx.y;

    for (int i = threadIdx.x; i < KK * DD; i += blockDim.x) {
        int k = i / DD, d = i - k * DD;
        s_mu[k * DP + d] = g_mu[b * KK * DD + i];
    }
    if (threadIdx.x < KK) s_var[threadIdx.x] = 0.0f;
    __syncthreads();

    const float* eb = emb  + (size_t)b * DD * NN;
    const int*   cb = cls  + (size_t)b * NN;
    const int*   ib = inst + (size_t)b * NN;

    const int stride2 = gridDim.x * blockDim.x;
    for (int n2 = blockIdx.x * blockDim.x + threadIdx.x; n2 < NN / 2; n2 += stride2) {
        int2 c2 = ((const int2*)cb)[n2];
        int2 i2 = ((const int2*)ib)[n2];
        int id0 = (c2.x == IGNORE_IDX) ? -1 : ((c2.x == 1) ? 0 : i2.x);
        int id1 = (c2.y == IGNORE_IDX) ? -1 : ((c2.y == 1) ? 0 : i2.y);
        const float* m0 = &s_mu[(id0 < 0 ? 0 : id0) * DP];
        const float* m1 = &s_mu[(id1 < 0 ? 0 : id1) * DP];

        float a0 = 0.0f, a1 = 0.0f;
        #pragma unroll
        for (int d = 0; d < DD; d++) {
            float2 v = ((const float2*)(eb + (size_t)d * NN))[n2];
            a0 += fabsf(v.x - m0[d]);
            a1 += fabsf(v.y - m1[d]);
        }
        if (id0 >= 0) { float h = fmaxf(a0 - DELTA_V, 0.0f); atomicAdd(&s_var[id0], h * h); }
        if (id1 >= 0) { float h = fmaxf(a1 - DELTA_V, 0.0f); atomicAdd(&s_var[id1], h * h); }
    }
    __syncthreads();
    if (threadIdx.x < KK) {
        float v = s_var[threadIdx.x];
        if (v != 0.0f) atomicAdd(&g_var[b * KK + threadIdx.x], v);
    }
}

// ---------------------------------------------------------------------------
__global__ void k_pass4(float* __restrict__ out, int out_size) {
    __shared__ float acc[4];
    if (threadIdx.x < 4) acc[threadIdx.x] = 0.0f;
    __syncthreads();
    if (threadIdx.x < BB) {
        const int b = threadIdx.x;
        float lvar = 0.0f;
        for (int k = 0; k < KK; k++)
            lvar += g_var[b * KK + k] / (g_cnt[b * KK + k] + 1e-8f);
        lvar /= g_ninst[b];
        float lv = 1.0f   * lvar;
        float ld = 1.0f   * g_ldist[b];
        float lr = 0.001f * g_lreg[b];
        float loss = lv + ld + lr;
        atomicAdd(&acc[0], loss / BB);
        atomicAdd(&acc[1], lv   / BB);
        atomicAdd(&acc[2], ld   / BB);
        atomicAdd(&acc[3], lr   / BB);
    }
    __syncthreads();
    if (threadIdx.x < 4 && threadIdx.x < out_size)
        out[threadIdx.x] = acc[threadIdx.x];
}

// ---------------------------------------------------------------------------
extern "C" void kernel_launch(void* const* d_in, const int* in_sizes, int n_in,
                              void* d_out, int out_size) {
    const float* emb  = (const float*)d_in[0];
    const int*   cls  = (const int*)  d_in[1];
    const int*   inst = (const int*)  d_in[2];
    float* out = (float*)d_out;

    (void)in_sizes; (void)n_in;

    // pass1 needs >48KB dynamic smem
    cudaFuncSetAttribute(k_pass1, cudaFuncAttributeMaxDynamicSharedMemorySize, SM_TOTAL);

    k_zero<<<(BB * KK * DD + 255) / 256, 256>>>();

    dim3 grid1(G1, BB);
    k_pass1<<<grid1, 256, SM_TOTAL>>>(emb, cls, inst);

    k_pass2<<<BB, 256>>>();

    dim3 grid3(128, BB);
    k_pass3<<<grid3, 256>>>(emb, cls, inst);

    k_pass4<<<1, 64>>>(out, out_size);
}

// round 11
// speedup vs baseline: 1.4980x; 1.0105x over previous
#include <cuda_runtime.h>
#include <cuda_bf16.h>

// Problem constants (fixed by setup_inputs)
#define BB 8
#define DD 32
#define NN 131072
#define KK 64
#define DP 33            // padded row for means in pass2/3
#define RR 8             // replication of global accumulator (contention spread)
#define IGNORE_IDX (-100)
#define DELTA_V 0.5f
#define DELTA_D 1.5f

// ---- scratch (allocation-free: __device__ globals) ----
__device__ float g_sum[RR * BB * KK * DD];   // replicated segment sums (512KB)
__device__ float g_cnt[BB * KK];
__device__ float g_mu [BB * KK * DD];
__device__ float g_var[BB * KK];
__device__ float g_ninst[BB];
__device__ float g_ldist[BB];
__device__ float g_lreg [BB];

// fire-and-forget vector reduction to global (REDG, no return value)
__device__ __forceinline__ void red_add_v4(float* p, float a, float b2, float c, float d) {
    asm volatile("red.global.add.v4.f32 [%0], {%1, %2, %3, %4};"
                 :: "l"(p), "f"(a), "f"(b2), "f"(c), "f"(d) : "memory");
}

// ---------------------------------------------------------------------------
__global__ void k_zero() {
    int t = blockIdx.x * blockDim.x + threadIdx.x;
    if (t < RR * BB * KK * DD) g_sum[t] = 0.0f;
    if (t < BB * KK) { g_cnt[t] = 0.0f; g_var[t] = 0.0f; }
    if (t < BB) { g_ninst[t] = 0.0f; g_ldist[t] = 0.0f; g_lreg[t] = 0.0f; }
}

// ---------------------------------------------------------------------------
// Pass 1 (v5): pass3-shaped streaming + L2 vector red-ops.
// - no smem tile, no per-chunk barriers: thread = 2 points (float2 over n),
//   32 coalesced float2 LDGs (high MLP), exactly the proven pass3 shape.
// - scatter: 8x red.global.add.v4.f32 per point into a REPLICATED global
//   accumulator (copy = blockIdx.x & 7) -> 4x fewer atomic lane-ops than the
//   smem-ATOMS v2, fire-and-forget on the LTS atomic ALUs, overlapped with
//   DRAM streaming, 8x less per-address contention.
// - counts: 1 smem atomic per point, flushed once per block.
// grid = (128, BB), block = 256.
__global__ void __launch_bounds__(256) k_pass1(const float* __restrict__ emb,
                                               const int*   __restrict__ cls,
                                               const int*   __restrict__ inst) {
    __shared__ float s_cnt[KK];
    const int b   = blockIdx.y;
    const int tid = threadIdx.x;

    if (tid < KK) s_cnt[tid] = 0.0f;
    __syncthreads();

    float* gsum = g_sum + (size_t)((blockIdx.x & (RR - 1)) * BB + b) * KK * DD;

    const float* eb = emb  + (size_t)b * DD * NN;
    const int*   cb = cls  + (size_t)b * NN;
    const int*   ib = inst + (size_t)b * NN;

    const int stride2 = gridDim.x * blockDim.x;
    for (int n2 = blockIdx.x * blockDim.x + tid; n2 < NN / 2; n2 += stride2) {
        int2 c2 = ((const int2*)cb)[n2];
        int2 i2 = ((const int2*)ib)[n2];
        int id0 = (c2.x == IGNORE_IDX) ? -1 : ((c2.x == 1) ? 0 : i2.x);
        int id1 = (c2.y == IGNORE_IDX) ? -1 : ((c2.y == 1) ? 0 : i2.y);
        if (id0 >= 0) atomicAdd(&s_cnt[id0], 1.0f);
        if (id1 >= 0) atomicAdd(&s_cnt[id1], 1.0f);

        float* r0 = gsum + (id0 < 0 ? 0 : id0) * DD;
        float* r1 = gsum + (id1 < 0 ? 0 : id1) * DD;

        #pragma unroll
        for (int j = 0; j < 8; j++) {
            float2 v0 = ((const float2*)(eb + (size_t)(4 * j + 0) * NN))[n2];
            float2 v1 = ((const float2*)(eb + (size_t)(4 * j + 1) * NN))[n2];
            float2 v2 = ((const float2*)(eb + (size_t)(4 * j + 2) * NN))[n2];
            float2 v3 = ((const float2*)(eb + (size_t)(4 * j + 3) * NN))[n2];
            if (id0 >= 0) red_add_v4(r0 + 4 * j, v0.x, v1.x, v2.x, v3.x);
            if (id1 >= 0) red_add_v4(r1 + 4 * j, v0.y, v1.y, v2.y, v3.y);
        }
    }
    __syncthreads();
    if (tid < KK) {
        float v = s_cnt[tid];
        if (v != 0.0f) atomicAdd(&g_cnt[b * KK + tid], v);
    }
}

// ---------------------------------------------------------------------------
// Pass 2: reduce replicas -> means, present mask, n_inst, pairwise hinge, reg.
__global__ void k_pass2() {
    const int b = blockIdx.x;
    const int tid = threadIdx.x;
    __shared__ float s_mu[KK * DP];
    __shared__ float s_cnt[KK];
    __shared__ int   s_pres[KK];
    __shared__ float red0[256], red1[256], red2[256];

    if (tid < KK) {
        float c = g_cnt[b * KK + tid];
        s_cnt[tid] = c;
        s_pres[tid] = (c > 0.0f) ? 1 : 0;
    }
    __syncthreads();

    for (int i = tid; i < KK * DD; i += blockDim.x) {
        int k = i / DD, d = i - k * DD;
        float s = 0.0f;
        #pragma unroll
        for (int r = 0; r < RR; r++)
            s += g_sum[(size_t)(r * BB + b) * KK * DD + i];
        float m = s / (s_cnt[k] + 1e-8f);
        g_mu[b * KK * DD + i] = m;
        s_mu[k * DP + d] = m;
    }
    __syncthreads();

    float np = 0.0f, lreg = 0.0f, ldist = 0.0f;
    for (int k = tid; k < KK; k += blockDim.x) np += (float)s_pres[k];
    for (int i = tid; i < KK * DD; i += blockDim.x) {
        int k = i / DD, d = i - k * DD;
        if (s_pres[k]) lreg += fabsf(s_mu[k * DP + d]);
    }
    for (int p = tid; p < KK * KK; p += blockDim.x) {
        int i = p >> 6, j = p & 63;
        if (i != j && s_pres[i] && s_pres[j]) {
            float dsum = 0.0f;
            #pragma unroll
            for (int d = 0; d < DD; d++)
                dsum += fabsf(s_mu[i * DP + d] - s_mu[j * DP + d]);
            float h = fmaxf(2.0f * DELTA_D - dsum, 0.0f);
            ldist += h * h;
        }
    }
    red0[tid] = np; red1[tid] = lreg; red2[tid] = ldist;
    __syncthreads();
    for (int off = 128; off > 0; off >>= 1) {
        if (tid < off) {
            red0[tid] += red0[tid + off];
            red1[tid] += red1[tid + off];
            red2[tid] += red2[tid + off];
        }
        __syncthreads();
    }
    if (tid == 0) {
        float npres  = red0[0];
        float n_inst = fmaxf(npres, 1.0f);
        float npairs = npres * npres - npres;
        g_ninst[b] = n_inst;
        g_lreg[b]  = red1[0] / n_inst;
        g_ldist[b] = (npairs > 0.0f) ? red2[0] / fmaxf(npairs, 1.0f) : 0.0f;
    }
}

// ---------------------------------------------------------------------------
// Pass 3 (anchor, best measured 28.1us / 68% DRAM): float2, 2 pts/thread.
__global__ void __launch_bounds__(256) k_pass3(const float* __restrict__ emb,
                                               const int*   __restrict__ cls,
                                               const int*   __restrict__ inst) {
    __shared__ float s_mu[KK * DP];
    __shared__ float s_var[KK];
    const int b = blockIdx.y;

    for (int i = threadIdx.x; i < KK * DD; i += blockDim.x) {
        int k = i / DD, d = i - k * DD;
        s_mu[k * DP + d] = g_mu[b * KK * DD + i];
    }
    if (threadIdx.x < KK) s_var[threadIdx.x] = 0.0f;
    __syncthreads();

    const float* eb = emb  + (size_t)b * DD * NN;
    const int*   cb = cls  + (size_t)b * NN;
    const int*   ib = inst + (size_t)b * NN;

    const int stride2 = gridDim.x * blockDim.x;
    for (int n2 = blockIdx.x * blockDim.x + threadIdx.x; n2 < NN / 2; n2 += stride2) {
        int2 c2 = ((const int2*)cb)[n2];
        int2 i2 = ((const int2*)ib)[n2];
        int id0 = (c2.x == IGNORE_IDX) ? -1 : ((c2.x == 1) ? 0 : i2.x);
        int id1 = (c2.y == IGNORE_IDX) ? -1 : ((c2.y == 1) ? 0 : i2.y);
        const float* m0 = &s_mu[(id0 < 0 ? 0 : id0) * DP];
        const float* m1 = &s_mu[(id1 < 0 ? 0 : id1) * DP];

        float a0 = 0.0f, a1 = 0.0f;
        #pragma unroll
        for (int d = 0; d < DD; d++) {
            float2 v = ((const float2*)(eb + (size_t)d * NN))[n2];
            a0 += fabsf(v.x - m0[d]);
            a1 += fabsf(v.y - m1[d]);
        }
        if (id0 >= 0) { float h = fmaxf(a0 - DELTA_V, 0.0f); atomicAdd(&s_var[id0], h * h); }
        if (id1 >= 0) { float h = fmaxf(a1 - DELTA_V, 0.0f); atomicAdd(&s_var[id1], h * h); }
    }
    __syncthreads();
    if (threadIdx.x < KK) {
        float v = s_var[threadIdx.x];
        if (v != 0.0f) atomicAdd(&g_var[b * KK + threadIdx.x], v);
    }
}

// ---------------------------------------------------------------------------
__global__ void k_pass4(float* __restrict__ out, int out_size) {
    __shared__ float acc[4];
    if (threadIdx.x < 4) acc[threadIdx.x] = 0.0f;
    __syncthreads();
    if (threadIdx.x < BB) {
        const int b = threadIdx.x;
        float lvar = 0.0f;
        for (int k = 0; k < KK; k++)
            lvar += g_var[b * KK + k] / (g_cnt[b * KK + k] + 1e-8f);
        lvar /= g_ninst[b];
        float lv = 1.0f   * lvar;
        float ld = 1.0f   * g_ldist[b];
        float lr = 0.001f * g_lreg[b];
        float loss = lv + ld + lr;
        atomicAdd(&acc[0], loss / BB);
        atomicAdd(&acc[1], lv   / BB);
        atomicAdd(&acc[2], ld   / BB);
        atomicAdd(&acc[3], lr   / BB);
    }
    __syncthreads();
    if (threadIdx.x < 4 && threadIdx.x < out_size)
        out[threadIdx.x] = acc[threadIdx.x];
}

// ---------------------------------------------------------------------------
extern "C" void kernel_launch(void* const* d_in, const int* in_sizes, int n_in,
                              void* d_out, int out_size) {
    const float* emb  = (const float*)d_in[0];
    const int*   cls  = (const int*)  d_in[1];
    const int*   inst = (const int*)  d_in[2];
    float* out = (float*)d_out;

    (void)in_sizes; (void)n_in;

    k_zero<<<(RR * BB * KK * DD + 255) / 256, 256>>>();

    dim3 grid1(128, BB);
    k_pass1<<<grid1, 256>>>(emb, cls, inst);

    k_pass2<<<BB, 256>>>();

    dim3 grid3(128, BB);
    k_pass3<<<grid3, 256>>>(emb, cls, inst);

    k_pass4<<<1, 64>>>(out, out_size);
}

// round 12
// speedup vs baseline: 1.5259x; 1.0186x over previous
#include <cuda_runtime.h>
#include <cuda_bf16.h>

// Problem constants (fixed by setup_inputs)
#define BB 8
#define DD 32
#define NN 131072
#define KK 64
#define DP 33            // padded row for means in pass2/3
#define G1X 128          // pass1 grid.x; one accumulator replica PER BLOCK
#define IGNORE_IDX (-100)
#define DELTA_V 0.5f
#define DELTA_D 1.5f

#define SUMSZ (G1X * BB * KK * DD)   // 2M floats = 8 MiB, L2-resident

// ---- scratch (allocation-free: __device__ globals) ----
__device__ float g_sum [SUMSZ];          // per-(block,batch) segment sums
__device__ float g_sum2[BB * KK * DD];   // reduced sums
__device__ float g_cnt[BB * KK];
__device__ float g_mu [BB * KK * DD];
__device__ float g_var[BB * KK];
__device__ float g_ninst[BB];
__device__ float g_ldist[BB];
__device__ float g_lreg [BB];

// fire-and-forget vector reduction to global (REDG, no return value)
__device__ __forceinline__ void red_add_v4(float* p, float a, float b2, float c, float d) {
    asm volatile("red.global.add.v4.f32 [%0], {%1, %2, %3, %4};"
                 :: "l"(p), "f"(a), "f"(b2), "f"(c), "f"(d) : "memory");
}

// ---------------------------------------------------------------------------
// Zero the 8 MiB accumulator (float4 stores) + small scratch.
__global__ void k_zero() {
    int t = blockIdx.x * blockDim.x + threadIdx.x;
    if (t < SUMSZ / 4) ((float4*)g_sum)[t] = make_float4(0.f, 0.f, 0.f, 0.f);
    if (t < BB * KK) { g_cnt[t] = 0.0f; g_var[t] = 0.0f; }
    if (t < BB) { g_ninst[t] = 0.0f; g_ldist[t] = 0.0f; g_lreg[t] = 0.0f; }
}

// ---------------------------------------------------------------------------
// Pass 1 (v6): pass3-shaped streaming + REDG.v4 into PER-BLOCK accumulators.
// replica = blockIdx.x -> zero cross-block address contention at LTS
// ("per-CTA-distinct addresses are 63x faster", B300 microarch).
// Within a block only 8 warps share 64 clusters -> n_conc ~1-2.
// grid = (G1X, BB), block = 256.
__global__ void __launch_bounds__(256) k_pass1(const float* __restrict__ emb,
                                               const int*   __restrict__ cls,
                                               const int*   __restrict__ inst) {
    __shared__ float s_cnt[KK];
    const int b   = blockIdx.y;
    const int tid = threadIdx.x;

    if (tid < KK) s_cnt[tid] = 0.0f;
    __syncthreads();

    float* gsum = g_sum + (size_t)(blockIdx.x * BB + b) * KK * DD;

    const float* eb = emb  + (size_t)b * DD * NN;
    const int*   cb = cls  + (size_t)b * NN;
    const int*   ib = inst + (size_t)b * NN;

    const int stride2 = gridDim.x * blockDim.x;
    for (int n2 = blockIdx.x * blockDim.x + tid; n2 < NN / 2; n2 += stride2) {
        int2 c2 = ((const int2*)cb)[n2];
        int2 i2 = ((const int2*)ib)[n2];
        int id0 = (c2.x == IGNORE_IDX) ? -1 : ((c2.x == 1) ? 0 : i2.x);
        int id1 = (c2.y == IGNORE_IDX) ? -1 : ((c2.y == 1) ? 0 : i2.y);
        if (id0 >= 0) atomicAdd(&s_cnt[id0], 1.0f);
        if (id1 >= 0) atomicAdd(&s_cnt[id1], 1.0f);

        float* r0 = gsum + (id0 < 0 ? 0 : id0) * DD;
        float* r1 = gsum + (id1 < 0 ? 0 : id1) * DD;

        #pragma unroll
        for (int j = 0; j < 8; j++) {
            float2 v0 = ((const float2*)(eb + (size_t)(4 * j + 0) * NN))[n2];
            float2 v1 = ((const float2*)(eb + (size_t)(4 * j + 1) * NN))[n2];
            float2 v2 = ((const float2*)(eb + (size_t)(4 * j + 2) * NN))[n2];
            float2 v3 = ((const float2*)(eb + (size_t)(4 * j + 3) * NN))[n2];
            if (id0 >= 0) red_add_v4(r0 + 4 * j, v0.x, v1.x, v2.x, v3.x);
            if (id1 >= 0) red_add_v4(r1 + 4 * j, v0.y, v1.y, v2.y, v3.y);
        }
    }
    __syncthreads();
    if (tid < KK) {
        float v = s_cnt[tid];
        if (v != 0.0f) atomicAdd(&g_cnt[b * KK + tid], v);
    }
}

// ---------------------------------------------------------------------------
// Reduce 128 per-block replicas -> g_sum2. thread t = (b,i); addresses
// t + r*16384 (64KB stride, L2-resident). grid = 64 x 256.
__global__ void k_reduce() {
    int t = blockIdx.x * blockDim.x + threadIdx.x;   // 0 .. BB*KK*DD-1
    float s = 0.0f;
    #pragma unroll 8
    for (int r = 0; r < G1X; r++)
        s += g_sum[(size_t)r * (BB * KK * DD) + t];
    g_sum2[t] = s;
}

// ---------------------------------------------------------------------------
// Pass 2: means, present mask, n_inst, pairwise hinge (l_dist), l_reg.
__global__ void k_pass2() {
    const int b = blockIdx.x;
    const int tid = threadIdx.x;
    __shared__ float s_mu[KK * DP];
    __shared__ float s_cnt[KK];
    __shared__ int   s_pres[KK];
    __shared__ float red0[256], red1[256], red2[256];

    if (tid < KK) {
        float c = g_cnt[b * KK + tid];
        s_cnt[tid] = c;
        s_pres[tid] = (c > 0.0f) ? 1 : 0;
    }
    __syncthreads();

    for (int i = tid; i < KK * DD; i += blockDim.x) {
        int k = i / DD, d = i - k * DD;
        float m = g_sum2[b * KK * DD + i] / (s_cnt[k] + 1e-8f);
        g_mu[b * KK * DD + i] = m;
        s_mu[k * DP + d] = m;
    }
    __syncthreads();

    float np = 0.0f, lreg = 0.0f, ldist = 0.0f;
    for (int k = tid; k < KK; k += blockDim.x) np += (float)s_pres[k];
    for (int i = tid; i < KK * DD; i += blockDim.x) {
        int k = i / DD, d = i - k * DD;
        if (s_pres[k]) lreg += fabsf(s_mu[k * DP + d]);
    }
    for (int p = tid; p < KK * KK; p += blockDim.x) {
        int i = p >> 6, j = p & 63;
        if (i != j && s_pres[i] && s_pres[j]) {
            float dsum = 0.0f;
            #pragma unroll
            for (int d = 0; d < DD; d++)
                dsum += fabsf(s_mu[i * DP + d] - s_mu[j * DP + d]);
            float h = fmaxf(2.0f * DELTA_D - dsum, 0.0f);
            ldist += h * h;
        }
    }
    red0[tid] = np; red1[tid] = lreg; red2[tid] = ldist;
    __syncthreads();
    for (int off = 128; off > 0; off >>= 1) {
        if (tid < off) {
            red0[tid] += red0[tid + off];
            red1[tid] += red1[tid + off];
            red2[tid] += red2[tid + off];
        }
        __syncthreads();
    }
    if (tid == 0) {
        float npres  = red0[0];
        float n_inst = fmaxf(npres, 1.0f);
        float npairs = npres * npres - npres;
        g_ninst[b] = n_inst;
        g_lreg[b]  = red1[0] / n_inst;
        g_ldist[b] = (npairs > 0.0f) ? red2[0] / fmaxf(npairs, 1.0f) : 0.0f;
    }
}

// ---------------------------------------------------------------------------
// Pass 3 (anchor, best measured 28.1us / 68% DRAM): float2, 2 pts/thread.
__global__ void __launch_bounds__(256) k_pass3(const float* __restrict__ emb,
                                               const int*   __restrict__ cls,
                                               const int*   __restrict__ inst) {
    __shared__ float s_mu[KK * DP];
    __shared__ float s_var[KK];
    const int b = blockIdx.y;

    for (int i = threadIdx.x; i < KK * DD; i += blockDim.x) {
        int k = i / DD, d = i - k * DD;
        s_mu[k * DP + d] = g_mu[b * KK * DD + i];
    }
    if (threadIdx.x < KK) s_var[threadIdx.x] = 0.0f;
    __syncthreads();

    const float* eb = emb  + (size_t)b * DD * NN;
    const int*   cb = cls  + (size_t)b * NN;
    const int*   ib = inst + (size_t)b * NN;

    const int stride2 = gridDim.x * blockDim.x;
    for (int n2 = blockIdx.x * blockDim.x + threadIdx.x; n2 < NN / 2; n2 += stride2) {
        int2 c2 = ((const int2*)cb)[n2];
        int2 i2 = ((const int2*)ib)[n2];
        int id0 = (c2.x == IGNORE_IDX) ? -1 : ((c2.x == 1) ? 0 : i2.x);
        int id1 = (c2.y == IGNORE_IDX) ? -1 : ((c2.y == 1) ? 0 : i2.y);
        const float* m0 = &s_mu[(id0 < 0 ? 0 : id0) * DP];
        const float* m1 = &s_mu[(id1 < 0 ? 0 : id1) * DP];

        float a0 = 0.0f, a1 = 0.0f;
        #pragma unroll
        for (int d = 0; d < DD; d++) {
            float2 v = ((const float2*)(eb + (size_t)d * NN))[n2];
            a0 += fabsf(v.x - m0[d]);
            a1 += fabsf(v.y - m1[d]);
        }
        if (id0 >= 0) { float h = fmaxf(a0 - DELTA_V, 0.0f); atomicAdd(&s_var[id0], h * h); }
        if (id1 >= 0) { float h = fmaxf(a1 - DELTA_V, 0.0f); atomicAdd(&s_var[id1], h * h); }
    }
    __syncthreads();
    if (threadIdx.x < KK) {
        float v = s_var[threadIdx.x];
        if (v != 0.0f) atomicAdd(&g_var[b * KK + threadIdx.x], v);
    }
}

// ---------------------------------------------------------------------------
__global__ void k_pass4(float* __restrict__ out, int out_size) {
    __shared__ float acc[4];
    if (threadIdx.x < 4) acc[threadIdx.x] = 0.0f;
    __syncthreads();
    if (threadIdx.x < BB) {
        const int b = threadIdx.x;
        float lvar = 0.0f;
        for (int k = 0; k < KK; k++)
            lvar += g_var[b * KK + k] / (g_cnt[b * KK + k] + 1e-8f);
        lvar /= g_ninst[b];
        float lv = 1.0f   * lvar;
        float ld = 1.0f   * g_ldist[b];
        float lr = 0.001f * g_lreg[b];
        float loss = lv + ld + lr;
        atomicAdd(&acc[0], loss / BB);
        atomicAdd(&acc[1], lv   / BB);
        atomicAdd(&acc[2], ld   / BB);
        atomicAdd(&acc[3], lr   / BB);
    }
    __syncthreads();
    if (threadIdx.x < 4 && threadIdx.x < out_size)
        out[threadIdx.x] = acc[threadIdx.x];
}

// ---------------------------------------------------------------------------
extern "C" void kernel_launch(void* const* d_in, const int* in_sizes, int n_in,
                              void* d_out, int out_size) {
    const float* emb  = (const float*)d_in[0];
    const int*   cls  = (const int*)  d_in[1];
    const int*   inst = (const int*)  d_in[2];
    float* out = (float*)d_out;

    (void)in_sizes; (void)n_in;

    k_zero<<<(SUMSZ / 4 + 255) / 256, 256>>>();

    dim3 grid1(G1X, BB);
    k_pass1<<<grid1, 256>>>(emb, cls, inst);

    k_reduce<<<(BB * KK * DD) / 256, 256>>>();

    k_pass2<<<BB, 256>>>();

    dim3 grid3(128, BB);
    k_pass3<<<grid3, 256>>>(emb, cls, inst);

    k_pass4<<<1, 64>>>(out, out_size);
}